// round 12
// baseline (speedup 1.0000x reference)
#include <cuda_runtime.h>
#include <cstdint>

#define NN    50000
#define OBS   15
#define H     64
#define NTHR  256
#define NCTA  296          // persistent CTAs (2 per SM)
#define WP    260          // transposed W_hh row stride (floats)
#define HD    8            // duplicated-h row width (floats per k)

typedef unsigned long long u64;

__device__ float    g_social[16 * H];
__device__ float    g_ht[H];        // final target-LSTM hidden state
__device__ unsigned g_cnt;
__device__ unsigned g_tick;
__device__ unsigned g_list[NN];     // packed: idx | (bin << 16)

// ---- packed fp32x2 helpers --------------------------------------------------
__device__ __forceinline__ u64 ffma2(u64 a, u64 b, u64 c) {
    u64 d; asm("fma.rn.f32x2 %0, %1, %2, %3;" : "=l"(d) : "l"(a), "l"(b), "l"(c));
    return d;
}
__device__ __forceinline__ u64 dup2(float x) {
    u64 d; asm("mov.b64 %0, {%1, %1};" : "=l"(d) : "f"(x)); return d;
}
__device__ __forceinline__ u64 pack2(float x, float y) {
    u64 d; asm("mov.b64 %0, {%1, %2};" : "=l"(d) : "f"(x), "f"(y)); return d;
}
__device__ __forceinline__ float2 unpack2(u64 a) {
    float2 r; asm("mov.b64 {%0, %1}, %2;" : "=f"(r.x), "=f"(r.y) : "l"(a)); return r;
}
// ---- activations ------------------------------------------------------------
__device__ __forceinline__ float tanh_ap(float x) {
    float y; asm("tanh.approx.f32 %0, %1;" : "=f"(y) : "f"(x)); return y;
}
__device__ __forceinline__ float sig_ap(float x) { return fmaf(0.5f, tanh_ap(0.5f * x), 0.5f); }
__device__ __forceinline__ float sigf(float x)   { return __fdividef(1.0f, 1.0f + __expf(-x)); }
__device__ __forceinline__ float tanhf_(float x) { return 2.0f * sigf(2.0f * x) - 1.0f; }

// ---------------------------------------------------------------------------
// Filter: keep neighbors with mask[14]!=0 inside the 4x4 window around
// tgt[14] — the only ones whose LSTM output is ever used.
// ---------------------------------------------------------------------------
__global__ void __launch_bounds__(256)
filter_kernel(const float* __restrict__ oth, const int* __restrict__ mask,
              const float* __restrict__ tgt)
{
    int n = blockIdx.x * blockDim.x + threadIdx.x;
    bool valid = false; int bin = 0;
    if (n < NN) {
        float2 xv = ((const float2*)oth)[(size_t)(OBS - 1) * NN + n];
        float rx = xv.x - tgt[(OBS - 1) * 2];
        float ry = xv.y - tgt[(OBS - 1) * 2 + 1];
        int m = mask[(size_t)(OBS - 1) * NN + n];
        bool within = (fabsf(rx) <= 2.0f) && (fabsf(ry) <= 2.0f);
        int cx = (int)truncf(rx) + 2;
        int cy = (int)truncf(ry) + 2;
        valid = within && cx >= 0 && cx < 4 && cy >= 0 && cy < 4 && (m != 0);
        bin = cy * 4 + cx;
    }
    unsigned ball = __ballot_sync(0xffffffffu, valid);
    int lane = threadIdx.x & 31;
    unsigned base = 0;
    if (lane == 0 && ball) base = atomicAdd(&g_cnt, (unsigned)__popc(ball));
    base = __shfl_sync(0xffffffffu, base, 0);
    if (valid) {
        int rank = __popc(ball & ((1u << lane) - 1u));
        g_list[base + rank] = (unsigned)n | ((unsigned)bin << 16);
    }
}

// ---------------------------------------------------------------------------
// Persistent neighbor LSTM, warp-autonomous 4-neighbor tickets, FFMA2 GEMM.
// acc pairs = (unit 2*lane, unit 2*lane+1) of one gate; the W multiplier pair
// is the float2 already in the transposed-W layout (zero packing movs); h is
// stored duplicated in smem so the h operand is a direct broadcast load.
// Warp 0 of CTA 0 first runs the target LSTM (exact activations, overlapped).
// ---------------------------------------------------------------------------
__global__ void __launch_bounds__(NTHR)
neighbor_kernel(const float* __restrict__ oth,   // (OBS, NN, 2)
                const float* __restrict__ tgt,   // (OBS, 1, 2)
                const float* __restrict__ W_ih,  // (256, 2)
                const float* __restrict__ b_ih,  // (256)
                const float* __restrict__ W_hh,  // (256, 64)
                const float* __restrict__ b_hh)  // (256)
{
    extern __shared__ float sm[];
    float* Ws   = sm;                 // [64][WP]  Ws[k][j] = W_hh[j][k]
    float* hsA  = Ws + H * WP;        // [8][64][HD] per-warp duplicated h
    float* bins = hsA + 8 * H * HD;   // [16*64]

    const int tid  = threadIdx.x;
    const int lane = tid & 31;
    const int wid  = tid >> 5;
    float* hw2 = hsA + wid * (H * HD);

    // stage W_hh transposed (once per CTA)
    for (int idx = tid; idx < 4 * H * H; idx += NTHR) {
        int j = idx >> 6, k = idx & 63;
        Ws[k * WP + j] = W_hh[idx];
    }
    for (int i = tid; i < 16 * H; i += NTHR) bins[i] = 0.0f;

    // packed per-thread gate constants: pair q = (row 64q+2lane, 64q+2lane+1)
    u64 bbp[4], wx0p[4], wx1p[4];
    #pragma unroll
    for (int q = 0; q < 4; q++) {
        int je = 64 * q + 2 * lane, jo = je + 1;
        bbp [q] = pack2(b_ih[je] + b_hh[je], b_ih[jo] + b_hh[jo]);
        wx0p[q] = pack2(W_ih[2 * je],     W_ih[2 * jo]);
        wx1p[q] = pack2(W_ih[2 * je + 1], W_ih[2 * jo + 1]);
    }
    __syncthreads();   // Ws ready

    // ---- target LSTM: warp 0 of CTA 0, overlapped with ticket work --------
    if (blockIdx.x == 0 && wid == 0) {
        float bbT[8], wT0[8], wT1[8];
        #pragma unroll
        for (int q = 0; q < 4; q++)
            #pragma unroll
            for (int u = 0; u < 2; u++) {
                int j = 64 * q + lane + 32 * u;
                bbT[2 * q + u] = b_ih[j] + b_hh[j];
                wT0[2 * q + u] = W_ih[2 * j];
                wT1[2 * q + u] = W_ih[2 * j + 1];
            }
        float h0 = 0.f, h1 = 0.f, c0 = 0.f, c1 = 0.f;
        for (int t = 0; t < OBS; t++) {
            float x0 = tgt[2 * t], x1 = tgt[2 * t + 1];
            float a[8];
            #pragma unroll
            for (int g = 0; g < 8; g++)
                a[g] = fmaf(wT1[g], x1, fmaf(wT0[g], x0, bbT[g]));
            #pragma unroll 4
            for (int k = 0; k < 32; k++) {
                float hk0 = __shfl_sync(0xffffffffu, h0, k);
                float hk1 = __shfl_sync(0xffffffffu, h1, k);
                #pragma unroll
                for (int g = 0; g < 8; g++) {
                    int j = 64 * (g >> 1) + lane + 32 * (g & 1);
                    a[g] = fmaf(Ws[k * WP + j], hk0, a[g]);
                    a[g] = fmaf(Ws[(k + 32) * WP + j], hk1, a[g]);
                }
            }
            float i0 = sigf(a[0]), f0 = sigf(a[2]), g0 = tanhf_(a[4]), o0 = sigf(a[6]);
            float i1 = sigf(a[1]), f1 = sigf(a[3]), g1 = tanhf_(a[5]), o1 = sigf(a[7]);
            c0 = fmaf(f0, c0, i0 * g0);  h0 = o0 * tanhf_(c0);
            c1 = fmaf(f1, c1, i1 * g1);  h1 = o1 * tanhf_(c1);
        }
        g_ht[lane]      = h0;
        g_ht[lane + 32] = h1;
    }

    const unsigned cnt = g_cnt;
    const float4 z4 = make_float4(0.f, 0.f, 0.f, 0.f);

    while (true) {
        unsigned tk = 0;
        if (lane == 0) tk = atomicAdd(&g_tick, 1u);
        tk = __shfl_sync(0xffffffffu, tk, 0);
        const unsigned base = tk * 4;
        if (base >= cnt) break;          // warp-uniform

        // slots + x(0): lanes 0..3 own one neighbor each
        unsigned pk = 0xffffffffu;
        float2 xv = make_float2(0.0f, 0.0f);
        if (lane < 4 && base + lane < cnt) {
            pk = g_list[base + lane];
            xv = ((const float2*)oth)[pk & 0xffffu];
        }

        // zero this warp's h rows (2*lane, 2*lane+1; duplicated layout)
        *(float4*)(hw2 + (2 * lane)     * HD)     = z4;
        *(float4*)(hw2 + (2 * lane)     * HD + 4) = z4;
        *(float4*)(hw2 + (2 * lane + 1) * HD)     = z4;
        *(float4*)(hw2 + (2 * lane + 1) * HD + 4) = z4;

        float creg[4][2];
        #pragma unroll
        for (int i = 0; i < 4; i++) { creg[i][0] = 0.0f; creg[i][1] = 0.0f; }

        #pragma unroll 1
        for (int t = 0; t < OBS; t++) {
            __syncwarp();   // h(t-1) writes visible

            float xi0[4], xi1[4];
            #pragma unroll
            for (int i = 0; i < 4; i++) {
                xi0[i] = __shfl_sync(0xffffffffu, xv.x, i);
                xi1[i] = __shfl_sync(0xffffffffu, xv.y, i);
            }
            // prefetch x(t+1)
            float2 xn = make_float2(0.0f, 0.0f);
            if (lane < 4 && t + 1 < OBS && pk != 0xffffffffu)
                xn = ((const float2*)oth)[(size_t)(t + 1) * NN + (pk & 0xffffu)];

            // acc pairs: acc2[i][q] = (gate q of unit 2lane, unit 2lane+1)
            u64 acc2[4][4];
            #pragma unroll
            for (int i = 0; i < 4; i++) {
                u64 xd0 = dup2(xi0[i]);
                u64 xd1 = dup2(xi1[i]);
                #pragma unroll
                for (int q = 0; q < 4; q++)
                    acc2[i][q] = ffma2(wx1p[q], xd1, ffma2(wx0p[q], xd0, bbp[q]));
            }

            const float* wcol = Ws + 2 * lane;
            #pragma unroll 8
            for (int k = 0; k < H; k++) {
                ulonglong2 ha = *(const ulonglong2*)(hw2 + k * HD);      // (h0,h0),(h1,h1)
                ulonglong2 hb = *(const ulonglong2*)(hw2 + k * HD + 4);  // (h2,h2),(h3,h3)
                u64 w0 = *(const u64*)(wcol + k * WP);
                u64 w1 = *(const u64*)(wcol + k * WP + 64);
                u64 w2 = *(const u64*)(wcol + k * WP + 128);
                u64 w3 = *(const u64*)(wcol + k * WP + 192);
                u64 hd[4] = {ha.x, ha.y, hb.x, hb.y};
                #pragma unroll
                for (int i = 0; i < 4; i++) {
                    acc2[i][0] = ffma2(w0, hd[i], acc2[i][0]);
                    acc2[i][1] = ffma2(w1, hd[i], acc2[i][1]);
                    acc2[i][2] = ffma2(w2, hd[i], acc2[i][2]);
                    acc2[i][3] = ffma2(w3, hd[i], acc2[i][3]);
                }
            }
            __syncwarp();   // all h reads done before overwrite

            float hnew[4][2];
            #pragma unroll
            for (int i = 0; i < 4; i++) {
                float2 I = unpack2(acc2[i][0]);
                float2 F = unpack2(acc2[i][1]);
                float2 G = unpack2(acc2[i][2]);
                float2 O = unpack2(acc2[i][3]);
                float c0 = fmaf(sig_ap(F.x), creg[i][0], sig_ap(I.x) * tanh_ap(G.x));
                float c1 = fmaf(sig_ap(F.y), creg[i][1], sig_ap(I.y) * tanh_ap(G.y));
                creg[i][0] = c0;  creg[i][1] = c1;
                hnew[i][0] = sig_ap(O.x) * tanh_ap(c0);
                hnew[i][1] = sig_ap(O.y) * tanh_ap(c1);
            }
            #pragma unroll
            for (int u = 0; u < 2; u++) {
                float4 A = make_float4(hnew[0][u], hnew[0][u], hnew[1][u], hnew[1][u]);
                float4 B = make_float4(hnew[2][u], hnew[2][u], hnew[3][u], hnew[3][u]);
                *(float4*)(hw2 + (2 * lane + u) * HD)     = A;
                *(float4*)(hw2 + (2 * lane + u) * HD + 4) = B;
            }
            xv = xn;
        }
        __syncwarp();

        // pooling: lane handles j = lane and j = lane+32 for the 4 neighbors
        #pragma unroll
        for (int i = 0; i < 4; i++) {
            unsigned pki = __shfl_sync(0xffffffffu, pk, i);
            if (pki != 0xffffffffu) {
                int bin = (int)(pki >> 16);
                atomicAdd(&bins[bin * H + lane],      hw2[lane * HD + 2 * i]);
                atomicAdd(&bins[bin * H + lane + 32], hw2[(lane + 32) * HD + 2 * i]);
            }
        }
    }
    __syncthreads();
    for (int i = tid; i < 16 * H; i += NTHR)
        atomicAdd(&g_social[i], bins[i]);
}

// ---------------------------------------------------------------------------
// MLP epilogue: ctx = relu(s1 @ W1^T + b1) @ W2^T + b2; out = Wc(h_t+ctx)+bc.
// ---------------------------------------------------------------------------
__global__ void __launch_bounds__(256)
mlp_kernel(const float* __restrict__ W1, const float* __restrict__ b1,
           const float* __restrict__ W2, const float* __restrict__ b2,
           const float* __restrict__ Wc, const float* __restrict__ bc,
           float* __restrict__ out)
{
    __shared__ float s1[16 * H], hid[H], comb[H];
    const int tid  = threadIdx.x;
    const int lane = tid & 31;
    const int wid  = tid >> 5;

    for (int i = tid; i < 16 * H; i += 256) s1[i] = g_social[i];
    __syncthreads();

    #pragma unroll
    for (int rr = 0; rr < 8; rr++) {
        int r = wid * 8 + rr;
        float p = 0.f;
        #pragma unroll 8
        for (int i = 0; i < 32; i++)
            p = fmaf(W1[r * 1024 + i * 32 + lane], s1[i * 32 + lane], p);
        #pragma unroll
        for (int off = 16; off; off >>= 1) p += __shfl_xor_sync(0xffffffffu, p, off);
        if (lane == 0) hid[r] = fmaxf(p + b1[r], 0.0f);
    }
    __syncthreads();

    #pragma unroll
    for (int rr = 0; rr < 8; rr++) {
        int r = wid * 8 + rr;
        float p = 0.f;
        #pragma unroll
        for (int i = 0; i < 2; i++)
            p = fmaf(W2[r * 64 + i * 32 + lane], hid[i * 32 + lane], p);
        #pragma unroll
        for (int off = 16; off; off >>= 1) p += __shfl_xor_sync(0xffffffffu, p, off);
        if (lane == 0) comb[r] = g_ht[r] + p + b2[r];
    }
    __syncthreads();

    if (wid < 2) {
        float p = 0.f;
        #pragma unroll
        for (int i = 0; i < 2; i++)
            p = fmaf(Wc[wid * 64 + i * 32 + lane], comb[i * 32 + lane], p);
        #pragma unroll
        for (int off = 16; off; off >>= 1) p += __shfl_xor_sync(0xffffffffu, p, off);
        if (lane == 0) out[wid] = p + bc[wid];
    }
}

// ---------------------------------------------------------------------------
extern "C" void kernel_launch(void* const* d_in, const int* in_sizes, int n_in,
                              void* d_out, int out_size)
{
    const float* tgt  = (const float*)d_in[0];
    const float* oth  = (const float*)d_in[1];
    const int*   mask = (const int*)  d_in[2];
    const float* W_ih = (const float*)d_in[3];
    const float* b_ih = (const float*)d_in[4];
    const float* W_hh = (const float*)d_in[5];
    const float* b_hh = (const float*)d_in[6];
    const float* W1   = (const float*)d_in[7];
    const float* b1   = (const float*)d_in[8];
    const float* W2   = (const float*)d_in[9];
    const float* b2   = (const float*)d_in[10];
    const float* Wc   = (const float*)d_in[11];
    const float* bc   = (const float*)d_in[12];

    void* p;
    cudaGetSymbolAddress(&p, g_social); cudaMemsetAsync(p, 0, 16 * H * sizeof(float));
    cudaGetSymbolAddress(&p, g_cnt);    cudaMemsetAsync(p, 0, sizeof(unsigned));
    cudaGetSymbolAddress(&p, g_tick);   cudaMemsetAsync(p, 0, sizeof(unsigned));

    const int smemN = (H * WP + 8 * H * HD + 16 * H) * 4;   // 87040 B
    cudaFuncSetAttribute((const void*)neighbor_kernel,
                         cudaFuncAttributeMaxDynamicSharedMemorySize, smemN);

    filter_kernel<<<(NN + 255) / 256, 256>>>(oth, mask, tgt);
    neighbor_kernel<<<NCTA, NTHR, smemN>>>(oth, tgt, W_ih, b_ih, W_hh, b_hh);
    mlp_kernel<<<1, 256>>>(W1, b1, W2, b2, Wc, bc, (float*)d_out);
}